// round 2
// baseline (speedup 1.0000x reference)
#include <cuda_runtime.h>

#define HID 128
#define KX 129          // 128 h-features + 1 agg column
#define M_TILE 128
#define THREADS 512

// Scratch (no cudaMalloc allowed): per-node aggregate.
// Zero-initialized at module load; mlp_kernel re-zeroes after reading, so the
// "g_agg is zero at entry to scatter" invariant holds across graph replays.
__device__ float g_agg[65536];

// ---------------------------------------------------------------------------
// packed fp32x2 helpers (FFMA2 — 2x fp32 FMA throughput on sm_103a)
// ---------------------------------------------------------------------------
__device__ __forceinline__ void fma2(unsigned long long& d,
                                     unsigned long long a,
                                     unsigned long long b) {
    asm("fma.rn.f32x2 %0, %1, %2, %0;" : "+l"(d) : "l"(a), "l"(b));
}
__device__ __forceinline__ unsigned long long dup2(float x) {
    unsigned long long r;
    unsigned xi = __float_as_uint(x);
    asm("mov.b64 %0, {%1, %1};" : "=l"(r) : "r"(xi));
    return r;
}
__device__ __forceinline__ float2 unpk(unsigned long long v) {
    unsigned lo, hi;
    asm("mov.b64 {%0, %1}, %2;" : "=r"(lo), "=r"(hi) : "l"(v));
    return make_float2(__uint_as_float(lo), __uint_as_float(hi));
}
__device__ __forceinline__ float silu(float x) {
    return x * (1.0f / (1.0f + __expf(-x)));
}

// ---------------------------------------------------------------------------
// Kernel 1: scatter-add distances into g_agg[row[e]].
// Edge dtype probed per block: jax randint(int64) silently demotes to int32
// when x64 is off. True int64 -> every odd 32-bit word is 0 (indices<50000).
// ---------------------------------------------------------------------------
__global__ void scatter_kernel(const int* __restrict__ edges_i32,
                               const float* __restrict__ dist, int E) {
    __shared__ int sstride;
    if (threadIdx.x == 0) {
        bool all_zero = true;
        int probe = E < 16 ? E : 16;
        for (int j = 0; j < probe; j++)
            if (edges_i32[2 * j + 1] != 0) { all_zero = false; break; }
        sstride = all_zero ? 2 : 1;
    }
    __syncthreads();
    int stride = sstride;
    int i = blockIdx.x * blockDim.x + threadIdx.x;
    if (i < E) {
        int r = edges_i32[(long long)i * stride];   // little-endian low word
        atomicAdd(&g_agg[r], dist[i]);
    }
}

// ---------------------------------------------------------------------------
// Kernel 2: fused node MLP with residual.
//   x[m, 0:128] = h[node], x[m,128] = agg[node]/100
//   t = silu(x @ W1 + b1);  out = h + t @ W2 + b2
//
// smem: w1s[129][128] | w2s[128][128] | xt[129][128] (swizzled, reused as tT)
//   xt element (k, m) at float index k*128 + ((m>>2) ^ ((k>>2)&31))*4 + (m&3)
//
// 512 threads, thread tile 4M x 8N:
//   nt = lane&15 (8 n-cols nt*8..+7), mt = (lane>>4)|(warp<<1) (4 m-rows mt*4..+3)
//   a-load: 1x LDS.128 (2 distinct addrs/warp -> broadcast)
//   b-load: 2x LDS.128 (16 distinct float4, halves dedup)
//   16 FFMA2 per k per thread; 4 warps/SMSP hide LDS latency.
// ---------------------------------------------------------------------------
__device__ __forceinline__ void gemm_groups(
    const float* __restrict__ xt, const float* __restrict__ ws,
    int ngroups, int mt, int nt, unsigned long long acc[4][4])
{
#pragma unroll 2
    for (int kg = 0; kg < ngroups; kg++) {
        int s = kg & 31;
        const float* xp = xt + (kg * 4) * HID + ((mt ^ s) << 2);
        const float* wp = ws + (kg * 4) * HID + (nt << 3);
#pragma unroll
        for (int kk = 0; kk < 4; kk++) {
            float4 a = *(const float4*)(xp + kk * HID);
            ulonglong2 bb0 = *(const ulonglong2*)(wp + kk * HID);
            ulonglong2 bb1 = *(const ulonglong2*)(wp + kk * HID + 4);
            unsigned long long ad[4];
            ad[0] = dup2(a.x); ad[1] = dup2(a.y);
            ad[2] = dup2(a.z); ad[3] = dup2(a.w);
            unsigned long long bp[4] = {bb0.x, bb0.y, bb1.x, bb1.y};
#pragma unroll
            for (int mi = 0; mi < 4; mi++)
#pragma unroll
                for (int np = 0; np < 4; np++) fma2(acc[mi][np], ad[mi], bp[np]);
        }
    }
}

__global__ void __launch_bounds__(THREADS, 1)
mlp_kernel(const float* __restrict__ h,
           const float* __restrict__ W1, const float* __restrict__ b1,
           const float* __restrict__ W2, const float* __restrict__ b2,
           float* __restrict__ out, int n_nodes, int n_tiles)
{
    extern __shared__ float smem[];
    float* w1s = smem;                         // 129*128
    float* w2s = smem + KX * HID;              // 128*128
    float* xt  = smem + KX * HID + HID * HID;  // 129*128 (swizzled)

    const int tid  = threadIdx.x;
    const int lane = tid & 31;
    const int warp = tid >> 5;
    const int nt   = lane & 15;                 // 8 N-cols: nt*8 .. nt*8+7
    const int mt   = (lane >> 4) | (warp << 1); // 0..31, 4 M-rows: mt*4 .. +3

    float b1r[8], b2r[8];
#pragma unroll
    for (int j = 0; j < 8; j++) {
        b1r[j] = b1[nt * 8 + j];
        b2r[j] = b2[nt * 8 + j];
    }

    // stage weights once per CTA (flat, coalesced float4)
    {
        const float4* g1 = (const float4*)W1;
        float4* s1 = (float4*)w1s;
        for (int i = tid; i < KX * HID / 4; i += THREADS) s1[i] = g1[i];
        const float4* g2 = (const float4*)W2;
        float4* s2 = (float4*)w2s;
        for (int i = tid; i < HID * HID / 4; i += THREADS) s2[i] = g2[i];
    }

    for (int tile = blockIdx.x; tile < n_tiles; tile += gridDim.x) {
        const int base = tile * M_TILE;
        __syncthreads();   // weights staged / previous tile's reads done

        // ---- fill xt[k][m] transposed+swizzled from h tile (coalesced) ----
        for (int mg = warp * 4; mg < M_TILE; mg += 64) {
            float4 r[4];
#pragma unroll
            for (int i = 0; i < 4; i++) {
                int gn = base + mg + i;
                r[i] = (gn < n_nodes)
                         ? __ldg((const float4*)&h[gn * HID + lane * 4])
                         : make_float4(0.f, 0.f, 0.f, 0.f);
            }
#pragma unroll
            for (int p = 0; p < 4; p++) {
                int k = lane * 4 + p;                 // k>>2 == lane
                float4 v = make_float4(((const float*)&r[0])[p],
                                       ((const float*)&r[1])[p],
                                       ((const float*)&r[2])[p],
                                       ((const float*)&r[3])[p]);
                int g = (mg >> 2) ^ lane;
                *(float4*)&xt[k * HID + g * 4] = v;
            }
        }
        // agg row k = 128 (swizzle term 0); also re-zero g_agg after reading
        if (tid < 32) {
            int gn = base + tid * 4;
            float4 av = make_float4(0.f, 0.f, 0.f, 0.f);
            if (gn + 0 < n_nodes) av.x = g_agg[gn + 0] * 0.01f;
            if (gn + 1 < n_nodes) av.y = g_agg[gn + 1] * 0.01f;
            if (gn + 2 < n_nodes) av.z = g_agg[gn + 2] * 0.01f;
            if (gn + 3 < n_nodes) av.w = g_agg[gn + 3] * 0.01f;
            *(float4*)&xt[128 * HID + tid * 4] = av;
            if (gn + 3 < n_nodes) {
                *(float4*)&g_agg[gn] = make_float4(0.f, 0.f, 0.f, 0.f);
            } else {
                if (gn + 0 < n_nodes) g_agg[gn + 0] = 0.f;
                if (gn + 1 < n_nodes) g_agg[gn + 1] = 0.f;
                if (gn + 2 < n_nodes) g_agg[gn + 2] = 0.f;
            }
        }
        __syncthreads();

        // ---- GEMM1: acc[mi][np] += x[k][m] * W1[k][n-pair], K = 129 ----
        unsigned long long acc[4][4];
#pragma unroll
        for (int mi = 0; mi < 4; mi++)
#pragma unroll
            for (int np = 0; np < 4; np++) acc[mi][np] = 0ull;

        gemm_groups(xt, w1s, 32, mt, nt, acc);
        {   // tail k = 128, swizzle s = (128>>2)&31 = 0
            const float* xp = xt + 128 * HID + (mt << 2);
            const float* wp = w1s + 128 * HID + (nt << 3);
            float4 a = *(const float4*)xp;
            ulonglong2 bb0 = *(const ulonglong2*)wp;
            ulonglong2 bb1 = *(const ulonglong2*)(wp + 4);
            unsigned long long ad[4];
            ad[0] = dup2(a.x); ad[1] = dup2(a.y);
            ad[2] = dup2(a.z); ad[3] = dup2(a.w);
            unsigned long long bp[4] = {bb0.x, bb0.y, bb1.x, bb1.y};
#pragma unroll
            for (int mi = 0; mi < 4; mi++)
#pragma unroll
                for (int np = 0; np < 4; np++) fma2(acc[mi][np], ad[mi], bp[np]);
        }
        __syncthreads();   // all xt reads done before overwriting as tT

        // ---- bias + silu + transposed store: tT[n][m] over xt buffer ----
#pragma unroll
        for (int j = 0; j < 8; j++) {
            int n = nt * 8 + j;
            float v[4];
#pragma unroll
            for (int mi = 0; mi < 4; mi++) {
                float2 p = unpk(acc[mi][j >> 1]);
                float x = ((j & 1) ? p.y : p.x) + b1r[j];
                v[mi] = silu(x);
            }
            int s = (n >> 2) & 31;
            *(float4*)&xt[n * HID + ((mt ^ s) << 2)] =
                make_float4(v[0], v[1], v[2], v[3]);
        }
        __syncthreads();

        // ---- GEMM2: acc2[mi][np] += t[k][m] * W2[k][n-pair], K = 128 ----
        unsigned long long acc2[4][4];
#pragma unroll
        for (int mi = 0; mi < 4; mi++)
#pragma unroll
            for (int np = 0; np < 4; np++) acc2[mi][np] = 0ull;

        gemm_groups(xt, w2s, 32, mt, nt, acc2);

        // ---- epilogue: out = h + u (residual), coalesced float4 ----
#pragma unroll
        for (int mi = 0; mi < 4; mi++) {
            int gn = base + mt * 4 + mi;
            if (gn < n_nodes) {
                const float4* hp = (const float4*)&h[gn * HID + nt * 8];
                float4 h0 = __ldg(hp), h1 = __ldg(hp + 1);
                float2 p0 = unpk(acc2[mi][0]);
                float2 p1 = unpk(acc2[mi][1]);
                float2 p2 = unpk(acc2[mi][2]);
                float2 p3 = unpk(acc2[mi][3]);
                float4 o0 = make_float4(h0.x + p0.x + b2r[0],
                                        h0.y + p0.y + b2r[1],
                                        h0.z + p1.x + b2r[2],
                                        h0.w + p1.y + b2r[3]);
                float4 o1 = make_float4(h1.x + p2.x + b2r[4],
                                        h1.y + p2.y + b2r[5],
                                        h1.z + p3.x + b2r[6],
                                        h1.w + p3.y + b2r[7]);
                float4* op = (float4*)&out[gn * HID + nt * 8];
                op[0] = o0;
                op[1] = o1;
            }
        }
    }
}

// ---------------------------------------------------------------------------
extern "C" void kernel_launch(void* const* d_in, const int* in_sizes, int n_in,
                              void* d_out, int out_size) {
    const float* h    = (const float*)d_in[0];
    const int*   edg  = (const int*)  d_in[1];   // int32 or int64 (detected)
    const float* dist = (const float*)d_in[2];
    const float* W1   = (const float*)d_in[9];   // W_n1 [129,128]
    const float* b1   = (const float*)d_in[10];  // b_n1 [128]
    const float* W2   = (const float*)d_in[11];  // W_n2 [128,128]
    const float* b2   = (const float*)d_in[12];  // b_n2 [128]
    float* out = (float*)d_out;

    int n_nodes = in_sizes[0] / HID;
    int E       = in_sizes[2];

    scatter_kernel<<<(E + 255) / 256, 256>>>(edg, dist, E);

    const int smem_bytes = (KX * HID + HID * HID + KX * HID) * (int)sizeof(float);
    cudaFuncSetAttribute(mlp_kernel,
                         cudaFuncAttributeMaxDynamicSharedMemorySize, smem_bytes);
    int sms = 148;
    cudaDeviceGetAttribute(&sms, cudaDevAttrMultiProcessorCount, 0);
    int n_tiles = (n_nodes + M_TILE - 1) / M_TILE;
    int grid = n_tiles < sms ? n_tiles : sms;
    mlp_kernel<<<grid, THREADS, smem_bytes>>>(h, W1, b1, W2, b2, out,
                                              n_nodes, n_tiles);
}

// round 4
// speedup vs baseline: 1.5076x; 1.5076x over previous
#include <cuda_runtime.h>
#include <mma.h>
#include <cstdint>

using namespace nvcuda;

#define HID     128
#define M_TILE  128
#define THREADS 256
#define LDS_    132     // padded row stride (floats): conflict-free ldmatrix

// Scratch: per-node aggregate. Zero at module load; mlp re-zeroes after
// reading so the invariant holds across CUDA-graph replays.
__device__ float g_agg[65536];

__device__ __forceinline__ float to_tf32(float x) {
    uint32_t u;
    asm("cvt.rna.tf32.f32 %0, %1;" : "=r"(u) : "f"(x));
    return __uint_as_float(u);
}
__device__ __forceinline__ float silu(float x) {
    return x * (1.0f / (1.0f + __expf(-x)));
}

// ---------------------------------------------------------------------------
// scatter-add distances into g_agg[row[e]].  Edge dtype probed: jax randint
// int64 silently demotes to int32 when x64 is off; true int64 buffers have
// all-zero high words (indices < 50000).
// ---------------------------------------------------------------------------
__global__ void scatter_kernel(const int* __restrict__ edges_i32,
                               const float* __restrict__ dist, int E) {
    __shared__ int sstride;
    if (threadIdx.x == 0) {
        bool all_zero = true;
        int probe = E < 16 ? E : 16;
        for (int j = 0; j < probe; j++)
            if (edges_i32[2 * j + 1] != 0) { all_zero = false; break; }
        sstride = all_zero ? 2 : 1;
    }
    __syncthreads();
    int stride = sstride;
    int i = blockIdx.x * blockDim.x + threadIdx.x;
    if (i < E) {
        int r = edges_i32[(long long)i * stride];
        atomicAdd(&g_agg[r], dist[i]);
    }
}

// ---------------------------------------------------------------------------
// 128x128x128 tf32 GEMM piece: acc[2][4] += X[warp rows] @ W[.][warp cols]
// X: [128 x 128] row-major (m x k), stride LDS_.  W: [128 x 128] (k x n).
// ---------------------------------------------------------------------------
using FragA = wmma::fragment<wmma::matrix_a, 16, 16, 8, wmma::precision::tf32,
                             wmma::row_major>;
using FragB = wmma::fragment<wmma::matrix_b, 16, 16, 8, wmma::precision::tf32,
                             wmma::row_major>;
using FragC = wmma::fragment<wmma::accumulator, 16, 16, 8, float>;

__device__ __forceinline__ void gemm_128(const float* __restrict__ xs,
                                         const float* __restrict__ ws,
                                         int wm, int wn, FragC acc[2][4]) {
#pragma unroll
    for (int i = 0; i < 2; i++)
#pragma unroll
        for (int j = 0; j < 4; j++) wmma::fill_fragment(acc[i][j], 0.0f);

#pragma unroll 4
    for (int k = 0; k < HID; k += 8) {
        FragA af[2];
        FragB bf[4];
#pragma unroll
        for (int i = 0; i < 2; i++)
            wmma::load_matrix_sync(af[i], xs + (wm * 32 + i * 16) * LDS_ + k, LDS_);
#pragma unroll
        for (int j = 0; j < 4; j++)
            wmma::load_matrix_sync(bf[j], ws + k * LDS_ + wn * 64 + j * 16, LDS_);
#pragma unroll
        for (int i = 0; i < 2; i++)
#pragma unroll
            for (int j = 0; j < 4; j++)
                wmma::mma_sync(acc[i][j], af[i], bf[j], acc[i][j]);
    }
}

// ---------------------------------------------------------------------------
// Fused node MLP:  t = silu(h@W1[:128] + agg*W1[128] + b1);  out = h + t@W2 + b2
// Weights tf32-rounded, smem-resident across tiles. Persistent CTAs.
// ---------------------------------------------------------------------------
__global__ void __launch_bounds__(THREADS, 1)
mlp_kernel(const float* __restrict__ h,
           const float* __restrict__ W1, const float* __restrict__ b1,
           const float* __restrict__ W2, const float* __restrict__ b2,
           float* __restrict__ out, int n_nodes, int n_tiles)
{
    extern __shared__ float smf[];
    float* w1s  = smf;                        // 128*LDS_
    float* w2s  = smf + 128 * LDS_;           // 128*LDS_
    float* xs   = smf + 2 * 128 * LDS_;       // 128*LDS_ (X / T / stage)
    float* w1r  = smf + 3 * 128 * LDS_;       // 128 (W1 row 128, fp32)
    float* b1s  = w1r + 128;
    float* b2s  = b1s + 128;
    float* sagg = b2s + 128;

    const int tid  = threadIdx.x;
    const int warp = tid >> 5;
    const int wm   = warp >> 1;   // 0..3 -> rows wm*32..+31
    const int wn   = warp & 1;    // 0..1 -> cols wn*64..+63

    // ---- stage weights once per CTA (tf32-rounded) ----
    for (int idx = tid; idx < 128 * 32; idx += THREADS) {
        int k = idx >> 5, c4 = (idx & 31) << 2;
        float4 v1 = __ldg((const float4*)&W1[k * HID + c4]);
        float4 v2 = __ldg((const float4*)&W2[k * HID + c4]);
        v1.x = to_tf32(v1.x); v1.y = to_tf32(v1.y);
        v1.z = to_tf32(v1.z); v1.w = to_tf32(v1.w);
        v2.x = to_tf32(v2.x); v2.y = to_tf32(v2.y);
        v2.z = to_tf32(v2.z); v2.w = to_tf32(v2.w);
        *(float4*)&w1s[k * LDS_ + c4] = v1;
        *(float4*)&w2s[k * LDS_ + c4] = v2;
    }
    if (tid < 32) {
        *(float4*)&w1r[tid * 4] = __ldg((const float4*)&W1[128 * HID + tid * 4]);
        *(float4*)&b1s[tid * 4] = __ldg((const float4*)&b1[tid * 4]);
        *(float4*)&b2s[tid * 4] = __ldg((const float4*)&b2[tid * 4]);
    }

    for (int tile = blockIdx.x; tile < n_tiles; tile += gridDim.x) {
        const int base = tile * M_TILE;
        __syncthreads();   // weights staged / prev tile's xs reads done

        // ---- fill X (tf32-rounded) + agg slice ----
        for (int idx = tid; idx < M_TILE * 32; idx += THREADS) {
            int m = idx >> 5, c4 = (idx & 31) << 2;
            int gn = base + m;
            float4 v = make_float4(0.f, 0.f, 0.f, 0.f);
            if (gn < n_nodes) {
                v = __ldg((const float4*)&h[(size_t)gn * HID + c4]);
                v.x = to_tf32(v.x); v.y = to_tf32(v.y);
                v.z = to_tf32(v.z); v.w = to_tf32(v.w);
            }
            *(float4*)&xs[m * LDS_ + c4] = v;
        }
        if (tid < 32) {
            int gn = base + tid * 4;
            float4 av = make_float4(0.f, 0.f, 0.f, 0.f);
            if (gn + 0 < n_nodes) { av.x = g_agg[gn + 0] * 0.01f; g_agg[gn + 0] = 0.f; }
            if (gn + 1 < n_nodes) { av.y = g_agg[gn + 1] * 0.01f; g_agg[gn + 1] = 0.f; }
            if (gn + 2 < n_nodes) { av.z = g_agg[gn + 2] * 0.01f; g_agg[gn + 2] = 0.f; }
            if (gn + 3 < n_nodes) { av.w = g_agg[gn + 3] * 0.01f; g_agg[gn + 3] = 0.f; }
            *(float4*)&sagg[tid * 4] = av;
        }
        __syncthreads();

        // ---- GEMM1: D1 = X @ W1k ----
        FragC acc[2][4];
        gemm_128(xs, w1s, wm, wn, acc);
        __syncthreads();   // all xs reads done before overwrite
#pragma unroll
        for (int i = 0; i < 2; i++)
#pragma unroll
            for (int j = 0; j < 4; j++)
                wmma::store_matrix_sync(
                    &xs[(wm * 32 + i * 16) * LDS_ + wn * 64 + j * 16],
                    acc[i][j], LDS_, wmma::mem_row_major);
        __syncthreads();

        // ---- epilogue1: t = tf32(silu(D1 + agg*w1r + b1)), in place ----
        for (int idx = tid; idx < M_TILE * 32; idx += THREADS) {
            int m = idx >> 5, c4 = (idx & 31) << 2;
            float aggv = sagg[m];
            float4 v = *(const float4*)&xs[m * LDS_ + c4];
            v.x = to_tf32(silu(v.x + aggv * w1r[c4 + 0] + b1s[c4 + 0]));
            v.y = to_tf32(silu(v.y + aggv * w1r[c4 + 1] + b1s[c4 + 1]));
            v.z = to_tf32(silu(v.z + aggv * w1r[c4 + 2] + b1s[c4 + 2]));
            v.w = to_tf32(silu(v.w + aggv * w1r[c4 + 3] + b1s[c4 + 3]));
            *(float4*)&xs[m * LDS_ + c4] = v;
        }
        __syncthreads();

        // ---- GEMM2: D2 = T @ W2 ----
        FragC acc2[2][4];
        gemm_128(xs, w2s, wm, wn, acc2);
        __syncthreads();
#pragma unroll
        for (int i = 0; i < 2; i++)
#pragma unroll
            for (int j = 0; j < 4; j++)
                wmma::store_matrix_sync(
                    &xs[(wm * 32 + i * 16) * LDS_ + wn * 64 + j * 16],
                    acc2[i][j], LDS_, wmma::mem_row_major);
        __syncthreads();

        // ---- writeback: out = h + D2 + b2 (coalesced float4) ----
        for (int idx = tid; idx < M_TILE * 32; idx += THREADS) {
            int m = idx >> 5, c4 = (idx & 31) << 2;
            int gn = base + m;
            if (gn < n_nodes) {
                float4 sv = *(const float4*)&xs[m * LDS_ + c4];
                float4 hv = __ldg((const float4*)&h[(size_t)gn * HID + c4]);
                *(float4*)&out[(size_t)gn * HID + c4] =
                    make_float4(hv.x + sv.x + b2s[c4 + 0],
                                hv.y + sv.y + b2s[c4 + 1],
                                hv.z + sv.z + b2s[c4 + 2],
                                hv.w + sv.w + b2s[c4 + 3]);
            }
        }
    }
}

// ---------------------------------------------------------------------------
extern "C" void kernel_launch(void* const* d_in, const int* in_sizes, int n_in,
                              void* d_out, int out_size) {
    const float* h    = (const float*)d_in[0];
    const int*   edg  = (const int*)  d_in[1];
    const float* dist = (const float*)d_in[2];
    const float* W1   = (const float*)d_in[9];   // W_n1 [129,128]
    const float* b1   = (const float*)d_in[10];
    const float* W2   = (const float*)d_in[11];  // W_n2 [128,128]
    const float* b2   = (const float*)d_in[12];
    float* out = (float*)d_out;

    int n_nodes = in_sizes[0] / HID;
    int E       = in_sizes[2];

    scatter_kernel<<<(E + 255) / 256, 256>>>(edg, dist, E);

    const int smem_bytes = (3 * 128 * LDS_ + 512) * (int)sizeof(float);  // ~204.8KB
    cudaFuncSetAttribute(mlp_kernel,
                         cudaFuncAttributeMaxDynamicSharedMemorySize, smem_bytes);
    int sms = 148;
    cudaDeviceGetAttribute(&sms, cudaDevAttrMultiProcessorCount, 0);
    int n_tiles = (n_nodes + M_TILE - 1) / M_TILE;
    int grid = n_tiles < sms ? n_tiles : sms;
    mlp_kernel<<<grid, THREADS, smem_bytes>>>(h, W1, b1, W2, b2, out,
                                              n_nodes, n_tiles);
}

// round 5
// speedup vs baseline: 1.6578x; 1.0997x over previous
#include <cuda_runtime.h>
#include <mma.h>
#include <cstdint>

using namespace nvcuda;

#define HID     128
#define M_TILE  128
#define THREADS 512
#define LDW     132     // W row stride (floats)
#define LDX     140     // X row stride (floats)
#define KPAD    136     // K extended: 128 feats + agg + ones + 6 zero pad

// Scratch: per-node aggregate. Zero at module load; mlp re-zeroes after
// reading so the invariant holds across CUDA-graph replays.
__device__ float g_agg[65536];

__device__ __forceinline__ float to_tf32(float x) {
    uint32_t u;
    asm("cvt.rna.tf32.f32 %0, %1;" : "=r"(u) : "f"(x));
    return __uint_as_float(u);
}
__device__ __forceinline__ float silu(float x) {
    return x * (1.0f / (1.0f + __expf(-x)));
}

// ---------------------------------------------------------------------------
// scatter-add distances into g_agg[row[e]].  Edge dtype probed: jax randint
// int64 silently demotes to int32 when x64 is off; true int64 buffers have
// all-zero high words (indices < 50000).
// ---------------------------------------------------------------------------
__global__ void scatter_kernel(const int* __restrict__ edges_i32,
                               const float* __restrict__ dist, int E) {
    __shared__ int sstride;
    if (threadIdx.x == 0) {
        bool all_zero = true;
        int probe = E < 16 ? E : 16;
        for (int j = 0; j < probe; j++)
            if (edges_i32[2 * j + 1] != 0) { all_zero = false; break; }
        sstride = all_zero ? 2 : 1;
    }
    __syncthreads();
    int stride = sstride;
    int i = blockIdx.x * blockDim.x + threadIdx.x;
    if (i < E) {
        int r = edges_i32[(long long)i * stride];
        atomicAdd(&g_agg[r], dist[i]);
    }
}

using FragA = wmma::fragment<wmma::matrix_a, 16, 16, 8, wmma::precision::tf32,
                             wmma::row_major>;
using FragB = wmma::fragment<wmma::matrix_b, 16, 16, 8, wmma::precision::tf32,
                             wmma::row_major>;
using FragC = wmma::fragment<wmma::accumulator, 16, 16, 8, float>;

// acc[2][2] += X[r0..r0+31][0..135] @ W[0..135][c0..c0+31]
__device__ __forceinline__ void gemm_ks(const float* __restrict__ xs,
                                        const float* __restrict__ ws,
                                        int r0, int c0, FragC acc[2][2]) {
#pragma unroll
    for (int k = 0; k < KPAD; k += 8) {
        FragA af[2];
        FragB bf[2];
        wmma::load_matrix_sync(af[0], xs + (size_t)r0 * LDX + k, LDX);
        wmma::load_matrix_sync(af[1], xs + (size_t)(r0 + 16) * LDX + k, LDX);
        wmma::load_matrix_sync(bf[0], ws + (size_t)k * LDW + c0, LDW);
        wmma::load_matrix_sync(bf[1], ws + (size_t)k * LDW + c0 + 16, LDW);
#pragma unroll
        for (int i = 0; i < 2; i++)
#pragma unroll
            for (int j = 0; j < 2; j++)
                wmma::mma_sync(acc[i][j], af[i], bf[j], acc[i][j]);
    }
}

// ---------------------------------------------------------------------------
// Fused node MLP:  t = silu([h, agg, 1] @ W1ext);  out = h + [t, 1] @ W2ext
// Bias and agg terms folded into the MMA K dimension. Persistent CTAs,
// weights smem-resident. 16 warps, 32x32 warp tiles.
// ---------------------------------------------------------------------------
__global__ void __launch_bounds__(THREADS, 1)
mlp_kernel(const float* __restrict__ h,
           const float* __restrict__ W1, const float* __restrict__ b1,
           const float* __restrict__ W2, const float* __restrict__ b2,
           float* __restrict__ out, int n_nodes, int n_tiles)
{
    extern __shared__ float smf[];
    float* w1s = smf;                       // [KPAD][LDW]
    float* w2s = smf + KPAD * LDW;          // [KPAD][LDW]
    float* xs  = smf + 2 * KPAD * LDW;      // [128][LDX] (X / T / slow stage)

    const int tid  = threadIdx.x;
    const int warp = tid >> 5;
    const int wm   = warp >> 2;    // 0..3 -> rows wm*32 .. +31
    const int wn   = warp & 3;     // 0..3 -> cols wn*32 .. +31
    const int r0   = wm * 32;
    const int c0   = wn * 32;

    // ---- stage extended weights once per CTA (tf32-rounded) ----
    for (int idx = tid; idx < KPAD * 32; idx += THREADS) {
        int k = idx >> 5, c4 = (idx & 31) << 2;
        float4 v1 = make_float4(0.f, 0.f, 0.f, 0.f);
        float4 v2 = make_float4(0.f, 0.f, 0.f, 0.f);
        if (k < 128) {
            v1 = __ldg((const float4*)&W1[k * HID + c4]);
            v2 = __ldg((const float4*)&W2[k * HID + c4]);
        } else if (k == 128) {
            v1 = __ldg((const float4*)&W1[128 * HID + c4]);   // agg row
            v2 = __ldg((const float4*)&b2[c4]);               // b2 row
        } else if (k == 129) {
            v1 = __ldg((const float4*)&b1[c4]);               // b1 row
        }
        v1.x = to_tf32(v1.x); v1.y = to_tf32(v1.y);
        v1.z = to_tf32(v1.z); v1.w = to_tf32(v1.w);
        v2.x = to_tf32(v2.x); v2.y = to_tf32(v2.y);
        v2.z = to_tf32(v2.z); v2.w = to_tf32(v2.w);
        *(float4*)&w1s[k * LDW + c4] = v1;
        *(float4*)&w2s[k * LDW + c4] = v2;
    }
    // X constant columns: col 129 = 1.0 (ones for b1), cols 130..135 = 0.
    if (tid < 128) {
        xs[tid * LDX + 129] = 1.0f;
#pragma unroll
        for (int c = 130; c < 136; c++) xs[tid * LDX + c] = 0.0f;
    }

    for (int tile = blockIdx.x; tile < n_tiles; tile += gridDim.x) {
        const int base = tile * M_TILE;
        const bool full = (base + M_TILE <= n_nodes);
        __syncthreads();   // prev tile's xs reads done before refill

        // ---- fill X cols 0..127 (tf32) + agg col 128, zero g_agg slice ----
        for (int idx = tid; idx < M_TILE * 32; idx += THREADS) {
            int m = idx >> 5, c4 = (idx & 31) << 2;
            int gn = base + m;
            float4 v = make_float4(0.f, 0.f, 0.f, 0.f);
            if (gn < n_nodes) {
                v = __ldg((const float4*)&h[(size_t)gn * HID + c4]);
                v.x = to_tf32(v.x); v.y = to_tf32(v.y);
                v.z = to_tf32(v.z); v.w = to_tf32(v.w);
            }
            *(float4*)&xs[m * LDX + c4] = v;
        }
        if (tid < 128) {
            int gn = base + tid;
            float a = 0.f;
            if (gn < n_nodes) { a = g_agg[gn] * 0.01f; g_agg[gn] = 0.f; }
            xs[tid * LDX + 128] = to_tf32(a);
        }
        __syncthreads();

        // ---- GEMM1: D1 = Xext @ W1ext  (K = 136) ----
        FragC acc[2][2];
#pragma unroll
        for (int i = 0; i < 2; i++)
#pragma unroll
            for (int j = 0; j < 2; j++) wmma::fill_fragment(acc[i][j], 0.0f);
        gemm_ks(xs, w1s, r0, c0, acc);

        // ---- silu on fragments (elementwise, position-independent) ----
#pragma unroll
        for (int i = 0; i < 2; i++)
#pragma unroll
            for (int j = 0; j < 2; j++)
#pragma unroll
                for (int e = 0; e < acc[i][j].num_elements; e++)
                    acc[i][j].x[e] = to_tf32(silu(acc[i][j].x[e]));

        __syncthreads();   // all GEMM1 xs reads done before T store

        // ---- store T into xs cols 0..127; col 128 becomes 1.0 (for b2) ----
#pragma unroll
        for (int i = 0; i < 2; i++)
#pragma unroll
            for (int j = 0; j < 2; j++)
                wmma::store_matrix_sync(&xs[(size_t)(r0 + i * 16) * LDX + c0 + j * 16],
                                        acc[i][j], LDX, wmma::mem_row_major);
        if (tid < 128) xs[tid * LDX + 128] = 1.0f;
        __syncthreads();

        // ---- GEMM2: out = h + Text @ W2ext ----
        FragC acc2[2][2];
        if (full) {
#pragma unroll
            for (int i = 0; i < 2; i++)
#pragma unroll
                for (int j = 0; j < 2; j++)
                    wmma::load_matrix_sync(acc2[i][j],
                        &h[(size_t)(base + r0 + i * 16) * HID + c0 + j * 16],
                        HID, wmma::mem_row_major);
        } else {
#pragma unroll
            for (int i = 0; i < 2; i++)
#pragma unroll
                for (int j = 0; j < 2; j++) wmma::fill_fragment(acc2[i][j], 0.0f);
        }
        gemm_ks(xs, w2s, r0, c0, acc2);

        if (full) {
            // direct register -> gmem store (residual already in acc2)
#pragma unroll
            for (int i = 0; i < 2; i++)
#pragma unroll
                for (int j = 0; j < 2; j++)
                    wmma::store_matrix_sync(
                        &out[(size_t)(base + r0 + i * 16) * HID + c0 + j * 16],
                        acc2[i][j], HID, wmma::mem_row_major);
        } else {
            // slow path (last partial tile only): stage in smem, guarded add
            __syncthreads();
#pragma unroll
            for (int i = 0; i < 2; i++)
#pragma unroll
                for (int j = 0; j < 2; j++)
                    wmma::store_matrix_sync(&xs[(size_t)(r0 + i * 16) * LDX + c0 + j * 16],
                                            acc2[i][j], LDX, wmma::mem_row_major);
            __syncthreads();
            for (int idx = tid; idx < M_TILE * 32; idx += THREADS) {
                int m = idx >> 5, c4 = (idx & 31) << 2;
                int gn = base + m;
                if (gn < n_nodes) {
                    float4 sv = *(const float4*)&xs[m * LDX + c4];
                    float4 hv = __ldg((const float4*)&h[(size_t)gn * HID + c4]);
                    *(float4*)&out[(size_t)gn * HID + c4] =
                        make_float4(hv.x + sv.x, hv.y + sv.y,
                                    hv.z + sv.z, hv.w + sv.w);
                }
            }
        }
    }
}

// ---------------------------------------------------------------------------
extern "C" void kernel_launch(void* const* d_in, const int* in_sizes, int n_in,
                              void* d_out, int out_size) {
    const float* h    = (const float*)d_in[0];
    const int*   edg  = (const int*)  d_in[1];
    const float* dist = (const float*)d_in[2];
    const float* W1   = (const float*)d_in[9];   // W_n1 [129,128]
    const float* b1   = (const float*)d_in[10];
    const float* W2   = (const float*)d_in[11];  // W_n2 [128,128]
    const float* b2   = (const float*)d_in[12];
    float* out = (float*)d_out;

    int n_nodes = in_sizes[0] / HID;
    int E       = in_sizes[2];

    scatter_kernel<<<(E + 255) / 256, 256>>>(edg, dist, E);

    const int smem_bytes = (2 * KPAD * LDW + 128 * LDX) * (int)sizeof(float);
    cudaFuncSetAttribute(mlp_kernel,
                         cudaFuncAttributeMaxDynamicSharedMemorySize, smem_bytes);
    int sms = 148;
    cudaDeviceGetAttribute(&sms, cudaDevAttrMultiProcessorCount, 0);
    int n_tiles = (n_nodes + M_TILE - 1) / M_TILE;
    int grid = n_tiles < sms ? n_tiles : sms;
    mlp_kernel<<<grid, THREADS, smem_bytes>>>(h, W1, b1, W2, b2, out,
                                              n_nodes, n_tiles);
}

// round 6
// speedup vs baseline: 3.1958x; 1.9277x over previous
#include <cuda_runtime.h>
#include <cuda_fp16.h>
#include <mma.h>
#include <cstdint>

using namespace nvcuda;

#define HID     128
#define M_TILE  128
#define THREADS 512
#define LDH     136     // half stride: 272B ≡ 16 mod 128 -> conflict-free LDSM

// Scratch: per-node aggregate. Zero at module load; mlp re-zeroes after
// reading so the invariant holds across CUDA-graph replays.
__device__ float g_agg[65536];

__device__ __forceinline__ float silu(float x) {
    return x * (1.0f / (1.0f + __expf(-x)));
}

// ---------------------------------------------------------------------------
// scatter-add distances into g_agg[row[e]], 4 edges per thread.
// Edge dtype probed: jax randint int64 silently demotes to int32 when x64 is
// off; true int64 buffers have all-zero high words (indices < 50000).
// ---------------------------------------------------------------------------
__global__ void scatter_kernel(const int* __restrict__ edges_i32,
                               const float* __restrict__ dist, int E) {
    __shared__ int sstride;
    if (threadIdx.x == 0) {
        bool all_zero = true;
        int probe = E < 16 ? E : 16;
        for (int j = 0; j < probe; j++)
            if (edges_i32[2 * j + 1] != 0) { all_zero = false; break; }
        sstride = all_zero ? 2 : 1;
    }
    __syncthreads();
    int stride = sstride;
    int i4 = (blockIdx.x * blockDim.x + threadIdx.x) * 4;
    if (i4 + 3 < E) {
        float4 d = __ldg((const float4*)&dist[i4]);
        int r0, r1, r2, r3;
        if (stride == 1) {
            int4 r = __ldg((const int4*)&edges_i32[i4]);
            r0 = r.x; r1 = r.y; r2 = r.z; r3 = r.w;
        } else {
            int4 ra = __ldg((const int4*)&edges_i32[2 * i4]);
            int4 rb = __ldg((const int4*)&edges_i32[2 * i4 + 4]);
            r0 = ra.x; r1 = ra.z; r2 = rb.x; r3 = rb.z;
        }
        atomicAdd(&g_agg[r0], d.x);
        atomicAdd(&g_agg[r1], d.y);
        atomicAdd(&g_agg[r2], d.z);
        atomicAdd(&g_agg[r3], d.w);
    } else {
        for (int j = i4; j < E; j++) {
            int r = edges_i32[(long long)j * stride];
            atomicAdd(&g_agg[r], dist[j]);
        }
    }
}

using FragA = wmma::fragment<wmma::matrix_a, 16, 16, 16, __half, wmma::row_major>;
using FragB = wmma::fragment<wmma::matrix_b, 16, 16, 16, __half, wmma::row_major>;
using FragC = wmma::fragment<wmma::accumulator, 16, 16, 16, float>;

// acc[2][2] += A[r0..r0+31][0..127] @ B[0..127][c0..c0+31], fp16 in smem,
// ping-pong software pipelined over 8 k16-steps.
__device__ __forceinline__ void gemm_fp16(const __half* __restrict__ as,
                                          const __half* __restrict__ bs,
                                          int r0, int c0, FragC acc[2][2]) {
    FragA af[2][2];
    FragB bf[2][2];
    wmma::load_matrix_sync(af[0][0], as + (size_t)r0 * LDH, LDH);
    wmma::load_matrix_sync(af[0][1], as + (size_t)(r0 + 16) * LDH, LDH);
    wmma::load_matrix_sync(bf[0][0], bs + c0, LDH);
    wmma::load_matrix_sync(bf[0][1], bs + c0 + 16, LDH);
#pragma unroll
    for (int ks = 0; ks < 8; ks++) {
        int cur = ks & 1, nxt = cur ^ 1;
        if (ks < 7) {
            int k = (ks + 1) * 16;
            wmma::load_matrix_sync(af[nxt][0], as + (size_t)r0 * LDH + k, LDH);
            wmma::load_matrix_sync(af[nxt][1], as + (size_t)(r0 + 16) * LDH + k, LDH);
            wmma::load_matrix_sync(bf[nxt][0], bs + (size_t)k * LDH + c0, LDH);
            wmma::load_matrix_sync(bf[nxt][1], bs + (size_t)k * LDH + c0 + 16, LDH);
        }
#pragma unroll
        for (int i = 0; i < 2; i++)
#pragma unroll
            for (int j = 0; j < 2; j++)
                wmma::mma_sync(acc[i][j], af[cur][i], bf[cur][j], acc[i][j]);
    }
}

// ---------------------------------------------------------------------------
// smem layout (bytes)
// ---------------------------------------------------------------------------
#define SM_W1H   0                      // half[128*LDH] 34816
#define SM_W2H   34816
#define SM_XH    69632
#define SM_TH    104448
#define SM_W1R   139264                 // f32[128]
#define SM_B1    139776
#define SM_B2    140288
#define SM_AGG   140800
#define SM_IOTA  141312                 // f32[256]
#define SM_TOTAL 142336

// ---------------------------------------------------------------------------
// Fused node MLP (fp16 tensor cores, fp32 accumulate):
//   t = silu(h@W1[:128] + agg*W1[128] + b1);  out = h + t@W2 + b2
// agg/bias/residual handled in fp32 register epilogues via iota-decoded
// fragment layout. Persistent CTAs, weights smem-resident, 3 syncs/tile.
// ---------------------------------------------------------------------------
__global__ void __launch_bounds__(THREADS, 1)
mlp_kernel(const float* __restrict__ h,
           const float* __restrict__ W1, const float* __restrict__ b1,
           const float* __restrict__ W2, const float* __restrict__ b2,
           float* __restrict__ out, int n_nodes, int n_tiles)
{
    extern __shared__ char sm[];
    __half* w1h = (__half*)(sm + SM_W1H);
    __half* w2h = (__half*)(sm + SM_W2H);
    __half* xh  = (__half*)(sm + SM_XH);
    __half* th  = (__half*)(sm + SM_TH);
    float*  w1r = (float*)(sm + SM_W1R);
    float*  b1s = (float*)(sm + SM_B1);
    float*  b2s = (float*)(sm + SM_B2);
    float*  sagg = (float*)(sm + SM_AGG);
    float*  iota = (float*)(sm + SM_IOTA);

    const int tid  = threadIdx.x;
    const int warp = tid >> 5;
    const int r0   = (warp >> 2) * 32;   // warp rows
    const int c0   = (warp & 3) * 32;    // warp cols

    // ---- stage weights (fp16) + vectors (fp32) once per CTA ----
    for (int idx = tid; idx < 128 * 32; idx += THREADS) {
        int k = idx >> 5, c4 = (idx & 31) << 2;
        float4 v1 = __ldg((const float4*)&W1[k * HID + c4]);
        float4 v2 = __ldg((const float4*)&W2[k * HID + c4]);
        __half2 p0 = __floats2half2_rn(v1.x, v1.y);
        __half2 p1 = __floats2half2_rn(v1.z, v1.w);
        __half2 q0 = __floats2half2_rn(v2.x, v2.y);
        __half2 q1 = __floats2half2_rn(v2.z, v2.w);
        uint2 pk, qk;
        pk.x = *reinterpret_cast<unsigned*>(&p0);
        pk.y = *reinterpret_cast<unsigned*>(&p1);
        qk.x = *reinterpret_cast<unsigned*>(&q0);
        qk.y = *reinterpret_cast<unsigned*>(&q1);
        *reinterpret_cast<uint2*>(&w1h[(size_t)k * LDH + c4]) = pk;
        *reinterpret_cast<uint2*>(&w2h[(size_t)k * LDH + c4]) = qk;
    }
    if (tid < 32) {
        *(float4*)&w1r[tid * 4] = __ldg((const float4*)&W1[128 * HID + tid * 4]);
        *(float4*)&b1s[tid * 4] = __ldg((const float4*)&b1[tid * 4]);
        *(float4*)&b2s[tid * 4] = __ldg((const float4*)&b2[tid * 4]);
    }
    if (tid < 256) iota[tid] = (float)tid;
    __syncthreads();

    // ---- decode accumulator fragment layout once (layout-agnostic) ----
    int dr[FragC::num_elements], dc[FragC::num_elements];
    {
        FragC idxf;
        wmma::load_matrix_sync(idxf, iota, 16, wmma::mem_row_major);
#pragma unroll
        for (int e = 0; e < idxf.num_elements; e++) {
            int v = __float2int_rn(idxf.x[e]);
            dr[e] = v >> 4;
            dc[e] = v & 15;
        }
    }

    for (int tile = blockIdx.x; tile < n_tiles; tile += gridDim.x) {
        const int base = tile * M_TILE;
        const bool full = (base + M_TILE <= n_nodes);
        __syncthreads();   // prior tile's xh/th reads complete

        // ---- fill X (fp16) + agg slice (fp32), re-zero g_agg ----
        for (int idx = tid; idx < M_TILE * 32; idx += THREADS) {
            int m = idx >> 5, c4 = (idx & 31) << 2;
            int gn = base + m;
            float4 v = make_float4(0.f, 0.f, 0.f, 0.f);
            if (gn < n_nodes) v = __ldg((const float4*)&h[(size_t)gn * HID + c4]);
            __half2 p0 = __floats2half2_rn(v.x, v.y);
            __half2 p1 = __floats2half2_rn(v.z, v.w);
            uint2 pk;
            pk.x = *reinterpret_cast<unsigned*>(&p0);
            pk.y = *reinterpret_cast<unsigned*>(&p1);
            *reinterpret_cast<uint2*>(&xh[(size_t)m * LDH + c4]) = pk;
        }
        if (tid < 128) {
            int gn = base + tid;
            float a = 0.f;
            if (gn < n_nodes) { a = g_agg[gn] * 0.01f; g_agg[gn] = 0.f; }
            sagg[tid] = a;
        }
        __syncthreads();

        // ---- GEMM1: D1 = X @ W1[:128] ----
        FragC acc[2][2];
#pragma unroll
        for (int i = 0; i < 2; i++)
#pragma unroll
            for (int j = 0; j < 2; j++) wmma::fill_fragment(acc[i][j], 0.0f);
        gemm_fp16(xh, w1h, r0, c0, acc);

        // ---- epilogue1 (fp32 regs): t = silu(D1 + agg[r]*w1r[c] + b1[c]) ----
        // th is a separate buffer: safe to write while others finish GEMM1.
#pragma unroll
        for (int i = 0; i < 2; i++)
#pragma unroll
            for (int j = 0; j < 2; j++)
#pragma unroll
                for (int e = 0; e < FragC::num_elements; e++) {
                    int r = r0 + i * 16 + dr[e];
                    int c = c0 + j * 16 + dc[e];
                    float v = acc[i][j].x[e] + sagg[r] * w1r[c] + b1s[c];
                    th[(size_t)r * LDH + c] = __float2half_rn(silu(v));
                }
        __syncthreads();   // T complete before GEMM2 reads

        // ---- GEMM2: out = h + T @ W2 + b2 (residual preloaded into acc) ----
        FragC acc2[2][2];
        if (full) {
#pragma unroll
            for (int i = 0; i < 2; i++)
#pragma unroll
                for (int j = 0; j < 2; j++)
                    wmma::load_matrix_sync(acc2[i][j],
                        &h[(size_t)(base + r0 + i * 16) * HID + c0 + j * 16],
                        HID, wmma::mem_row_major);
        } else {
#pragma unroll
            for (int i = 0; i < 2; i++)
#pragma unroll
                for (int j = 0; j < 2; j++) wmma::fill_fragment(acc2[i][j], 0.0f);
        }
        gemm_fp16(th, w2h, r0, c0, acc2);

        if (full) {
#pragma unroll
            for (int i = 0; i < 2; i++)
#pragma unroll
                for (int j = 0; j < 2; j++) {
#pragma unroll
                    for (int e = 0; e < FragC::num_elements; e++)
                        acc2[i][j].x[e] += b2s[c0 + j * 16 + dc[e]];
                    wmma::store_matrix_sync(
                        &out[(size_t)(base + r0 + i * 16) * HID + c0 + j * 16],
                        acc2[i][j], HID, wmma::mem_row_major);
                }
        } else {
            // partial last tile: guarded scalar writes (residual added here)
#pragma unroll
            for (int i = 0; i < 2; i++)
#pragma unroll
                for (int j = 0; j < 2; j++)
#pragma unroll
                    for (int e = 0; e < FragC::num_elements; e++) {
                        int gn = base + r0 + i * 16 + dr[e];
                        int c  = c0 + j * 16 + dc[e];
                        if (gn < n_nodes)
                            out[(size_t)gn * HID + c] =
                                __ldg(&h[(size_t)gn * HID + c]) +
                                acc2[i][j].x[e] + b2s[c];
                    }
        }
    }
}

// ---------------------------------------------------------------------------
extern "C" void kernel_launch(void* const* d_in, const int* in_sizes, int n_in,
                              void* d_out, int out_size) {
    const float* h    = (const float*)d_in[0];
    const int*   edg  = (const int*)  d_in[1];
    const float* dist = (const float*)d_in[2];
    const float* W1   = (const float*)d_in[9];   // W_n1 [129,128]
    const float* b1   = (const float*)d_in[10];
    const float* W2   = (const float*)d_in[11];  // W_n2 [128,128]
    const float* b2   = (const float*)d_in[12];
    float* out = (float*)d_out;

    int n_nodes = in_sizes[0] / HID;
    int E       = in_sizes[2];

    int sblocks = ((E + 3) / 4 + 255) / 256;
    scatter_kernel<<<sblocks, 256>>>(edg, dist, E);

    cudaFuncSetAttribute(mlp_kernel,
                         cudaFuncAttributeMaxDynamicSharedMemorySize, SM_TOTAL);
    int sms = 148;
    cudaDeviceGetAttribute(&sms, cudaDevAttrMultiProcessorCount, 0);
    int n_tiles = (n_nodes + M_TILE - 1) / M_TILE;
    int grid = n_tiles < sms ? n_tiles : sms;
    mlp_kernel<<<grid, THREADS, SM_TOTAL>>>(h, W1, b1, W2, b2, out,
                                            n_nodes, n_tiles);
}

// round 7
// speedup vs baseline: 3.2193x; 1.0074x over previous
#include <cuda_runtime.h>
#include <cuda_fp16.h>
#include <mma.h>
#include <cstdint>

using namespace nvcuda;

#define HID     128
#define M_TILE  128
#define THREADS 512
#define LDH     136     // half stride: 272B ≡ 16 mod 128 -> conflict-free LDSM

// Scratch: per-node aggregate. Zero at module load; mlp re-zeroes after
// reading so the invariant holds across CUDA-graph replays.
__device__ float g_agg[65536];

__device__ __forceinline__ float silu(float x) {
    return x * (1.0f / (1.0f + __expf(-x)));
}

// ---------------------------------------------------------------------------
// scatter-add distances into g_agg[row[e]], 4 edges per thread.
// Edge dtype probed: jax randint int64 silently demotes to int32 when x64 is
// off; true int64 buffers have all-zero high words (indices < 50000).
// ---------------------------------------------------------------------------
__global__ void scatter_kernel(const int* __restrict__ edges_i32,
                               const float* __restrict__ dist, int E) {
    __shared__ int sstride;
    if (threadIdx.x == 0) {
        bool all_zero = true;
        int probe = E < 16 ? E : 16;
        for (int j = 0; j < probe; j++)
            if (edges_i32[2 * j + 1] != 0) { all_zero = false; break; }
        sstride = all_zero ? 2 : 1;
    }
    __syncthreads();
    int stride = sstride;
    int i4 = (blockIdx.x * blockDim.x + threadIdx.x) * 4;
    if (i4 + 3 < E) {
        float4 d = __ldg((const float4*)&dist[i4]);
        int r0, r1, r2, r3;
        if (stride == 1) {
            int4 r = __ldg((const int4*)&edges_i32[i4]);
            r0 = r.x; r1 = r.y; r2 = r.z; r3 = r.w;
        } else {
            int4 ra = __ldg((const int4*)&edges_i32[2 * i4]);
            int4 rb = __ldg((const int4*)&edges_i32[2 * i4 + 4]);
            r0 = ra.x; r1 = ra.z; r2 = rb.x; r3 = rb.z;
        }
        atomicAdd(&g_agg[r0], d.x);
        atomicAdd(&g_agg[r1], d.y);
        atomicAdd(&g_agg[r2], d.z);
        atomicAdd(&g_agg[r3], d.w);
    } else {
        for (int j = i4; j < E; j++) {
            int r = edges_i32[(long long)j * stride];
            atomicAdd(&g_agg[r], dist[j]);
        }
    }
}

using FragA = wmma::fragment<wmma::matrix_a, 16, 16, 16, __half, wmma::row_major>;
using FragB = wmma::fragment<wmma::matrix_b, 16, 16, 16, __half, wmma::row_major>;
using FragC = wmma::fragment<wmma::accumulator, 16, 16, 16, float>;

// acc[2][2] += A[r0..+31][0..127] @ B[0..127][c0..+31], fp16 smem, ping-pong.
__device__ __forceinline__ void gemm_fp16(const __half* __restrict__ as,
                                          const __half* __restrict__ bs,
                                          int r0, int c0, FragC acc[2][2]) {
    FragA af[2][2];
    FragB bf[2][2];
    wmma::load_matrix_sync(af[0][0], as + (size_t)r0 * LDH, LDH);
    wmma::load_matrix_sync(af[0][1], as + (size_t)(r0 + 16) * LDH, LDH);
    wmma::load_matrix_sync(bf[0][0], bs + c0, LDH);
    wmma::load_matrix_sync(bf[0][1], bs + c0 + 16, LDH);
#pragma unroll
    for (int ks = 0; ks < 8; ks++) {
        int cur = ks & 1, nxt = cur ^ 1;
        if (ks < 7) {
            int k = (ks + 1) * 16;
            wmma::load_matrix_sync(af[nxt][0], as + (size_t)r0 * LDH + k, LDH);
            wmma::load_matrix_sync(af[nxt][1], as + (size_t)(r0 + 16) * LDH + k, LDH);
            wmma::load_matrix_sync(bf[nxt][0], bs + (size_t)k * LDH + c0, LDH);
            wmma::load_matrix_sync(bf[nxt][1], bs + (size_t)k * LDH + c0 + 16, LDH);
        }
#pragma unroll
        for (int i = 0; i < 2; i++)
#pragma unroll
            for (int j = 0; j < 2; j++)
                wmma::mma_sync(acc[i][j], af[cur][i], bf[cur][j], acc[i][j]);
    }
}

// ---------------------------------------------------------------------------
// smem layout (bytes)
// ---------------------------------------------------------------------------
#define SM_W1H   0                      // half[128*LDH] 34816
#define SM_W2H   34816
#define SM_XH    69632
#define SM_TH    104448
#define SM_STAGE 139264                 // f32[128][128] = 65536
#define SM_W1R   204800                 // f32[128]
#define SM_B1    205312
#define SM_B2    205824
#define SM_AGG   206336
#define SM_IOTA  206848                 // f32[256]
#define SM_TOTAL 207872

// cp.async 16B with zero-fill when src_sz == 0
__device__ __forceinline__ void cp_async16(void* dst_smem, const void* src, int src_sz) {
    unsigned d = (unsigned)__cvta_generic_to_shared(dst_smem);
    asm volatile("cp.async.cg.shared.global [%0], [%1], 16, %2;"
                 :: "r"(d), "l"(src), "r"(src_sz));
}
__device__ __forceinline__ void cp_commit() {
    asm volatile("cp.async.commit_group;" ::: "memory");
}
__device__ __forceinline__ void cp_wait0() {
    asm volatile("cp.async.wait_group 0;" ::: "memory");
}

// issue the fp32 h-tile load for `tile` into stage
__device__ __forceinline__ void issue_stage(float* stagef, const float* h,
                                            int base, int n_nodes, int tid) {
#pragma unroll
    for (int t = 0; t < 8; t++) {
        int idx = tid + t * THREADS;           // 0..4095
        int m = idx >> 5, c4 = (idx & 31) << 2;
        int gn = base + m;
        int ok = (gn < n_nodes);
        const float* src = h + (size_t)(ok ? gn : 0) * HID + c4;
        cp_async16(&stagef[m * HID + c4], src, ok ? 16 : 0);
    }
    cp_commit();
}

// ---------------------------------------------------------------------------
// Fused node MLP (fp16 TC, fp32 accum), cp.async tile pipeline:
//   t = silu(h@W1[:128] + agg*W1[128] + b1);  out = h + t@W2 + b2
// ---------------------------------------------------------------------------
__global__ void __launch_bounds__(THREADS, 1)
mlp_kernel(const float* __restrict__ h,
           const float* __restrict__ W1, const float* __restrict__ b1,
           const float* __restrict__ W2, const float* __restrict__ b2,
           float* __restrict__ out, int n_nodes, int n_tiles)
{
    extern __shared__ char sm[];
    __half* w1h   = (__half*)(sm + SM_W1H);
    __half* w2h   = (__half*)(sm + SM_W2H);
    __half* xh    = (__half*)(sm + SM_XH);
    __half* th    = (__half*)(sm + SM_TH);
    float*  stagef = (float*)(sm + SM_STAGE);
    float*  w1r   = (float*)(sm + SM_W1R);
    float*  b1s   = (float*)(sm + SM_B1);
    float*  b2s   = (float*)(sm + SM_B2);
    float*  sagg  = (float*)(sm + SM_AGG);
    float*  iota  = (float*)(sm + SM_IOTA);

    const int tid  = threadIdx.x;
    const int warp = tid >> 5;
    const int r0   = (warp >> 2) * 32;
    const int c0   = (warp & 3) * 32;

    // prologue: start streaming tile 0's h before anything else
    if (blockIdx.x < n_tiles)
        issue_stage(stagef, h, blockIdx.x * M_TILE, n_nodes, tid);

    // ---- stage weights (fp16) + vectors (fp32) once per CTA ----
    for (int idx = tid; idx < 128 * 32; idx += THREADS) {
        int k = idx >> 5, c4 = (idx & 31) << 2;
        float4 v1 = __ldg((const float4*)&W1[k * HID + c4]);
        float4 v2 = __ldg((const float4*)&W2[k * HID + c4]);
        __half2 p0 = __floats2half2_rn(v1.x, v1.y);
        __half2 p1 = __floats2half2_rn(v1.z, v1.w);
        __half2 q0 = __floats2half2_rn(v2.x, v2.y);
        __half2 q1 = __floats2half2_rn(v2.z, v2.w);
        uint2 pk, qk;
        pk.x = *reinterpret_cast<unsigned*>(&p0);
        pk.y = *reinterpret_cast<unsigned*>(&p1);
        qk.x = *reinterpret_cast<unsigned*>(&q0);
        qk.y = *reinterpret_cast<unsigned*>(&q1);
        *reinterpret_cast<uint2*>(&w1h[(size_t)k * LDH + c4]) = pk;
        *reinterpret_cast<uint2*>(&w2h[(size_t)k * LDH + c4]) = qk;
    }
    if (tid < 32) {
        *(float4*)&w1r[tid * 4] = __ldg((const float4*)&W1[128 * HID + tid * 4]);
        *(float4*)&b1s[tid * 4] = __ldg((const float4*)&b1[tid * 4]);
        *(float4*)&b2s[tid * 4] = __ldg((const float4*)&b2[tid * 4]);
    }
    if (tid < 256) iota[tid] = (float)tid;
    __syncthreads();

    // decode accumulator fragment layout once (layout-agnostic)
    int dr[FragC::num_elements], dc[FragC::num_elements];
    {
        FragC idxf;
        wmma::load_matrix_sync(idxf, iota, 16, wmma::mem_row_major);
#pragma unroll
        for (int e = 0; e < idxf.num_elements; e++) {
            int v = __float2int_rn(idxf.x[e]);
            dr[e] = v >> 4;
            dc[e] = v & 15;
        }
    }

    for (int tile = blockIdx.x; tile < n_tiles; tile += gridDim.x) {
        const int base = tile * M_TILE;
        const int next = tile + gridDim.x;
        const bool full = (base + M_TILE <= n_nodes);

        cp_wait0();
        __syncthreads();   // stage ready; previous th reads complete

        // ---- convert stage (fp32) -> xh (fp16); agg slice ----
#pragma unroll
        for (int t = 0; t < 8; t++) {
            int idx = tid + t * THREADS;
            int m = idx >> 5, c4 = (idx & 31) << 2;
            float4 v = *(const float4*)&stagef[m * HID + c4];
            __half2 p0 = __floats2half2_rn(v.x, v.y);
            __half2 p1 = __floats2half2_rn(v.z, v.w);
            uint2 pk;
            pk.x = *reinterpret_cast<unsigned*>(&p0);
            pk.y = *reinterpret_cast<unsigned*>(&p1);
            *reinterpret_cast<uint2*>(&xh[(size_t)m * LDH + c4]) = pk;
        }
        if (tid < 128) {
            int gn = base + tid;
            float a = 0.f;
            if (gn < n_nodes) { a = g_agg[gn] * 0.01f; g_agg[gn] = 0.f; }
            sagg[tid] = a;
        }
        __syncthreads();

        // ---- GEMM1: D1 = X @ W1[:128] ----
        FragC acc[2][2];
#pragma unroll
        for (int i = 0; i < 2; i++)
#pragma unroll
            for (int j = 0; j < 2; j++) wmma::fill_fragment(acc[i][j], 0.0f);
        gemm_fp16(xh, w1h, r0, c0, acc);

        // ---- epilogue1 (fp32 regs): t = silu(D1 + agg[r]*w1r[c] + b1[c]) ----
#pragma unroll
        for (int i = 0; i < 2; i++)
#pragma unroll
            for (int j = 0; j < 2; j++)
#pragma unroll
                for (int e = 0; e < FragC::num_elements; e++) {
                    int r = r0 + i * 16 + dr[e];
                    int c = c0 + j * 16 + dc[e];
                    float v = acc[i][j].x[e] + sagg[r] * w1r[c] + b1s[c];
                    th[(size_t)r * LDH + c] = __float2half_rn(silu(v));
                }

        // ---- residual from stage (fp32, still valid) into acc2 ----
        FragC acc2[2][2];
#pragma unroll
        for (int i = 0; i < 2; i++)
#pragma unroll
            for (int j = 0; j < 2; j++)
                wmma::load_matrix_sync(acc2[i][j],
                    &stagef[(size_t)(r0 + i * 16) * HID + c0 + j * 16],
                    HID, wmma::mem_row_major);

        __syncthreads();   // th complete; all stage reads done

        // ---- start streaming next tile's h into stage ----
        if (next < n_tiles) issue_stage(stagef, h, next * M_TILE, n_nodes, tid);

        // ---- GEMM2: out = residual + T @ W2 (+ b2) ----
        gemm_fp16(th, w2h, r0, c0, acc2);

        if (full) {
#pragma unroll
            for (int i = 0; i < 2; i++)
#pragma unroll
                for (int j = 0; j < 2; j++) {
#pragma unroll
                    for (int e = 0; e < FragC::num_elements; e++)
                        acc2[i][j].x[e] += b2s[c0 + j * 16 + dc[e]];
                    wmma::store_matrix_sync(
                        &out[(size_t)(base + r0 + i * 16) * HID + c0 + j * 16],
                        acc2[i][j], HID, wmma::mem_row_major);
                }
        } else {
            // partial last tile: guarded scalar stores (residual already in acc2)
#pragma unroll
            for (int i = 0; i < 2; i++)
#pragma unroll
                for (int j = 0; j < 2; j++)
#pragma unroll
                    for (int e = 0; e < FragC::num_elements; e++) {
                        int gn = base + r0 + i * 16 + dr[e];
                        int c  = c0 + j * 16 + dc[e];
                        if (gn < n_nodes)
                            out[(size_t)gn * HID + c] = acc2[i][j].x[e] + b2s[c];
                    }
        }
    }
}

// ---------------------------------------------------------------------------
extern "C" void kernel_launch(void* const* d_in, const int* in_sizes, int n_in,
                              void* d_out, int out_size) {
    const float* h    = (const float*)d_in[0];
    const int*   edg  = (const int*)  d_in[1];
    const float* dist = (const float*)d_in[2];
    const float* W1   = (const float*)d_in[9];   // W_n1 [129,128]
    const float* b1   = (const float*)d_in[10];
    const float* W2   = (const float*)d_in[11];  // W_n2 [128,128]
    const float* b2   = (const float*)d_in[12];
    float* out = (float*)d_out;

    int n_nodes = in_sizes[0] / HID;
    int E       = in_sizes[2];

    int sblocks = ((E + 3) / 4 + 255) / 256;
    scatter_kernel<<<sblocks, 256>>>(edg, dist, E);

    cudaFuncSetAttribute(mlp_kernel,
                         cudaFuncAttributeMaxDynamicSharedMemorySize, SM_TOTAL);
    int sms = 148;
    cudaDeviceGetAttribute(&sms, cudaDevAttrMultiProcessorCount, 0);
    int n_tiles = (n_nodes + M_TILE - 1) / M_TILE;
    int grid = n_tiles < sms ? n_tiles : sms;
    mlp_kernel<<<grid, THREADS, SM_TOTAL>>>(h, W1, b1, W2, b2, out,
                                            n_nodes, n_tiles);
}